// round 15
// baseline (speedup 1.0000x reference)
#include <cuda_runtime.h>
#include <cuda_bf16.h>
#include <math.h>
#include <stdint.h>

#define BATCH 32
#define TSTEPS 256
#define DIN 256
#define HID 1024
#define NOUT 4096
#define MROWS (BATCH*TSTEPS)   // 8192
#define NTILES (NOUT/8)        // 512
#define NB 128                 // persistent grid size
#define EPSV 1e-5f

typedef unsigned int u32;

// ---------------------------------------------------------------------------
// Static device scratch (no allocations anywhere)
// ---------------------------------------------------------------------------
__device__ float           g_Z[(size_t)MROWS * NOUT];
__device__ __nv_bfloat16   g_Shi[(size_t)MROWS * DIN];
__device__ __nv_bfloat16   g_Slo[(size_t)MROWS * DIN];
__device__ __nv_bfloat16   g_hs_hi[(size_t)MROWS * HID];
__device__ __nv_bfloat16   g_hs_lo[(size_t)MROWS * HID];

// Fragment-swizzled weights: flat = ((kt*NTILES + nt)*32 + lane)*4 + j
__device__ __nv_bfloat16   g_W0x_hi[(size_t)DIN*NOUT], g_W0x_lo[(size_t)DIN*NOUT];
__device__ __nv_bfloat16   g_W0h_hi[(size_t)HID*NOUT], g_W0h_lo[(size_t)HID*NOUT];
__device__ __nv_bfloat16   g_W1x_hi[(size_t)HID*NOUT], g_W1x_lo[(size_t)HID*NOUT];
__device__ __nv_bfloat16   g_W1h_hi[(size_t)HID*NOUT], g_W1h_lo[(size_t)HID*NOUT];

// h fragments, hi/lo interleaved: unit u = (mt*64+kt)*32+lane owns
// g_hf[u*16 .. u*16+7] = hi uint4, g_hf[u*16+8 .. u*16+15] = lo uint4 (32 B unit)
__device__ __nv_bfloat16   g_hf[BATCH*HID*2];

// Spread barrier: 8 counters, 256 B apart (stride 64 u32). Block bid -> bid&7.
__device__ unsigned        g_cnt[8 * 64];
__device__ float           g_part[BATCH][NB][2];

// ---------------------------------------------------------------------------
// Primitives
// ---------------------------------------------------------------------------
__device__ __forceinline__ void mma_bf16(float acc[4], const u32 a[4], u32 b0, u32 b1) {
    asm volatile(
        "mma.sync.aligned.m16n8k16.row.col.f32.bf16.bf16.f32 "
        "{%0,%1,%2,%3},{%4,%5,%6,%7},{%8,%9},{%0,%1,%2,%3};\n"
        : "+f"(acc[0]), "+f"(acc[1]), "+f"(acc[2]), "+f"(acc[3])
        : "r"(a[0]), "r"(a[1]), "r"(a[2]), "r"(a[3]), "r"(b0), "r"(b1));
}

__device__ __forceinline__ void split_f32(float v, __nv_bfloat16& hi, __nv_bfloat16& lo) {
    hi = __float2bfloat16(v);
    lo = __float2bfloat16(v - __bfloat162float(hi));
}

__device__ __forceinline__ unsigned ld_acq(const unsigned* p) {
    unsigned v;
    asm volatile("ld.acquire.gpu.global.u32 %0, [%1];" : "=r"(v) : "l"(p) : "memory");
    return v;
}
__device__ __forceinline__ void red_rel_add1(unsigned* p) {
    asm volatile("red.release.gpu.global.add.u32 [%0], 1;" :: "l"(p) : "memory");
}

// Fast transcendentals (MUFU-based).
__device__ __forceinline__ float fast_exp(float x) { return __expf(x); }
__device__ __forceinline__ float fast_tanh(float x) {
    float e = __expf(2.f * x);
    return 1.f - __fdividef(2.f, e + 1.f);
}
__device__ __forceinline__ float fast_sigmoid(float x) {
    return __fdividef(1.f, 1.f + __expf(-x));
}

// ---------------------------------------------------------------------------
// Weight split, fragment-vectorized: one thread per (matrix, kt, nt, lane).
// ---------------------------------------------------------------------------
__global__ void k_split_all(const float* __restrict__ W0, const float* __restrict__ W1) {
    int tid = blockIdx.x * blockDim.x + threadIdx.x;
    const int f0 = (DIN / 16) * NTILES * 32;   // 262144
    const int f1 = (HID / 16) * NTILES * 32;   // 1048576
    if (tid >= f0 + 3 * f1) return;
    const float* W; int row0, fi;
    __nv_bfloat16 *dh, *dl;
    if (tid < f0)            { W = W0; row0 = 0;   dh = g_W0x_hi; dl = g_W0x_lo; fi = tid; }
    else if (tid < f0 + f1)  { W = W0; row0 = DIN; dh = g_W0h_hi; dl = g_W0h_lo; fi = tid - f0; }
    else if (tid < f0 + 2*f1){ W = W1; row0 = 0;   dh = g_W1x_hi; dl = g_W1x_lo; fi = tid - f0 - f1; }
    else                     { W = W1; row0 = HID; dh = g_W1h_hi; dl = g_W1h_lo; fi = tid - f0 - 2*f1; }
    int lane = fi & 31;
    int nt = (fi >> 5) & (NTILES - 1);
    int kt = fi >> 14;
    int n = nt * 8 + (lane >> 2);
    int l = lane & 3;
    ushort hb[4], lb[4];
    #pragma unroll
    for (int j = 0; j < 4; j++) {
        int kr = 2 * l + (j & 1) + ((j >> 1) << 3);
        float wv = W[(size_t)(row0 + kt * 16 + kr) * NOUT + n];
        __nv_bfloat16 hi, lo; split_f32(wv, hi, lo);
        hb[j] = __bfloat16_as_ushort(hi);
        lb[j] = __bfloat16_as_ushort(lo);
    }
    size_t base = (((size_t)kt * NTILES + nt) * 32 + lane) * 4;
    uint2 hv = make_uint2((u32)hb[0] | ((u32)hb[1] << 16), (u32)hb[2] | ((u32)hb[3] << 16));
    uint2 lv = make_uint2((u32)lb[0] | ((u32)lb[1] << 16), (u32)lb[2] | ((u32)lb[3] << 16));
    *(uint2*)(dh + base) = hv;
    *(uint2*)(dl + base) = lv;
}

// series [B,T,D] -> row-major [t*32+b, d] hi/lo
__global__ void k_split_series(const float* __restrict__ S) {
    int idx = blockIdx.x * blockDim.x + threadIdx.x;
    if (idx >= MROWS * DIN) return;
    int row = idx / DIN, d = idx - row * DIN;
    int t = row >> 5, b = row & 31;
    float v = S[((size_t)b * TSTEPS + t) * DIN + d];
    __nv_bfloat16 hi, lo; split_f32(v, hi, lo);
    g_Shi[idx] = hi; g_Slo[idx] = lo;
}

// ---------------------------------------------------------------------------
// Pregemm (R12 config): M128 x N128 tiles, 512 thr (+ state init in tail)
// ---------------------------------------------------------------------------
__global__ __launch_bounds__(512) void k_pregemm(int which, const float* __restrict__ bias) {
    if (blockIdx.y == gridDim.y - 1 && blockIdx.x < 32) {
        int i = (blockIdx.x * 512 + threadIdx.x) * 4;
        __nv_bfloat16 z = __float2bfloat16(0.f);
        #pragma unroll
        for (int j = 0; j < 4; j++) g_hf[i + j] = z;
        if (blockIdx.x == 0 && threadIdx.x < 8) g_cnt[threadIdx.x * 64] = 0;
    }

    const __nv_bfloat16 *Ah, *Al, *Wh, *Wl;
    int K;
    if (which == 0) { Ah = g_Shi; Al = g_Slo; Wh = g_W0x_hi; Wl = g_W0x_lo; K = DIN; }
    else            { Ah = g_hs_hi; Al = g_hs_lo; Wh = g_W1x_hi; Wl = g_W1x_lo; K = HID; }
    const int KT = K >> 4;

    int w = threadIdx.x >> 5, lane = threadIdx.x & 31;
    int ng = w & 1, mt = w >> 1;
    int m0 = blockIdx.y * 128, n0 = blockIdx.x * 128;
    int nt_base = (n0 >> 3) + ng * 8;

    float acc[8][4] = {};
    int rbase = m0 + mt * 16 + (lane >> 2);
    int cb = (lane & 3) << 1;

    #pragma unroll 2
    for (int kt = 0; kt < KT; kt++) {
        int c0 = kt * 16 + cb;
        const __nv_bfloat16* pa0 = Ah + (size_t)rbase * K + c0;
        const __nv_bfloat16* pa1 = Ah + (size_t)(rbase + 8) * K + c0;
        const __nv_bfloat16* pl0 = Al + (size_t)rbase * K + c0;
        const __nv_bfloat16* pl1 = Al + (size_t)(rbase + 8) * K + c0;
        u32 ah[4], al[4];
        ah[0] = *(const u32*)(pa0);     ah[1] = *(const u32*)(pa1);
        ah[2] = *(const u32*)(pa0 + 8); ah[3] = *(const u32*)(pa1 + 8);
        al[0] = *(const u32*)(pl0);     al[1] = *(const u32*)(pl1);
        al[2] = *(const u32*)(pl0 + 8); al[3] = *(const u32*)(pl1 + 8);
        #pragma unroll
        for (int q = 0; q < 8; q++) {
            size_t fb = (((size_t)kt * NTILES + (nt_base + q)) * 32 + lane) * 4;
            uint2 bh = *(const uint2*)(Wh + fb);
            uint2 bl = *(const uint2*)(Wl + fb);
            mma_bf16(acc[q], ah, bh.x, bh.y);
            mma_bf16(acc[q], ah, bl.x, bl.y);
            mma_bf16(acc[q], al, bh.x, bh.y);
        }
    }
    int r = rbase;
    #pragma unroll
    for (int q = 0; q < 8; q++) {
        int ncol = (nt_base + q) * 8 + cb;
        float b0v = bias[ncol], b1v = bias[ncol + 1];
        float* p0 = g_Z + (size_t)r * NOUT + ncol;
        float* p1 = g_Z + (size_t)(r + 8) * NOUT + ncol;
        p0[0] = acc[q][0] + b0v;  p0[1] = acc[q][1] + b1v;
        p1[0] = acc[q][2] + b0v;  p1[1] = acc[q][3] + b1v;
    }
}

// ---------------------------------------------------------------------------
// Grid barrier: 8 spread counters (best measured)
// ---------------------------------------------------------------------------
__device__ __forceinline__ void grid_bar(unsigned& ncalls) {
    ncalls += 1;
    __syncthreads();
    if (threadIdx.x < 32) {
        if (threadIdx.x == 0) red_rel_add1(&g_cnt[(blockIdx.x & 7) * 64]);
        unsigned tgt = ncalls * 16;
        const unsigned* p = &g_cnt[(threadIdx.x & 7) * 64];
        for (;;) {
            unsigned v = ld_acq(p);
            if (__all_sync(0xffffffffu, v >= tgt)) break;
        }
    }
    __syncthreads();
}

// ---------------------------------------------------------------------------
// Persistent recurrence: 128 blocks x 512 thr (16 warps). R12 structure,
// h fragments hi/lo interleaved (same 128B line per fragment pair).
// ---------------------------------------------------------------------------
extern __shared__ uint4 s_dynW[];   // [4 gates][64 kt][32 lanes] uint4 = 128 KB

__global__ __launch_bounds__(512, 1) void k_recur(int layer,
                                                  const float* __restrict__ gamma,
                                                  const float* __restrict__ beta,
                                                  float* __restrict__ out) {
    const __nv_bfloat16* Wh = layer ? g_W1h_hi : g_W0h_hi;
    const __nv_bfloat16* Wl = layer ? g_W1h_lo : g_W0h_lo;
    const int bid = blockIdx.x;
    const int tid = threadIdx.x;

    for (int i = tid; i < 4 * 64 * 32; i += 512) {
        int lane = i & 31, kt = (i >> 5) & 63, g = i >> 11;
        size_t fb = (((size_t)kt * NTILES + (g * 128 + bid)) * 32 + lane);
        uint2 h2 = ((const uint2*)Wh)[fb];
        uint2 l2 = ((const uint2*)Wl)[fb];
        s_dynW[i] = make_uint4(h2.x, h2.y, l2.x, l2.y);
    }

    __shared__ float zsm[8][4][32][8];        // [ks][gate][row][col] partials

    const int w = tid >> 5, lane = tid & 31;
    const int mt = w & 1, ks = w >> 1;

    const int er = lane >> 2, ec = (lane & 3) << 1;
    const int em = mt * 16 + er;

    const int tb = (tid & 255) >> 3, tn = tid & 7;
    const int hidx = bid * 8 + tn;
    const float gam = gamma[hidx], bet = beta[hidx];
    float c_reg = 0.f;
    const int fmt = tb >> 4, fr = tb & 15, fkt = hidx >> 4, fc = hidx & 15;
    const int flane = (fr & 7) * 4 + ((fc & 7) >> 1);
    const int freg = ((fr >> 3) & 1) + ((fc >> 3) << 1);
    // interleaved unit: hi at u*16 + j, lo at u*16 + 8 + j
    const size_t funit = (((size_t)fmt * 64 + fkt) * 32 + flane) * 16;
    const int fj = freg * 2 + (fc & 1);

    unsigned ncalls = 0;
    __syncthreads();

    for (int t = 0; t < TSTEPS; t++) {
        // prefetch zx for scalar phase (independent of h; g_Z never stale)
        float zx_g[4];
        if (tid < 256) {
            const float* zrow = g_Z + ((size_t)t * BATCH + tb) * NOUT + hidx;
            #pragma unroll
            for (int g = 0; g < 4; g++) zx_g[g] = zrow[g * 1024];
        }

        // ---- partial z = h @ Wh for k-slice ks, all 4 gates ----
        float acc[4][2][4] = {};
        #pragma unroll 2
        for (int kq = 0; kq < 8; kq++) {
            int kt = ks * 8 + kq;
            size_t ua = (((size_t)mt * 64 + kt) * 32 + lane) * 16;
            uint4 vh = __ldcg((const uint4*)(g_hf + ua));
            uint4 vl = __ldcg((const uint4*)(g_hf + ua + 8));
            u32 AH[4] = {vh.x, vh.y, vh.z, vh.w};
            u32 AL[4] = {vl.x, vl.y, vl.z, vl.w};
            #pragma unroll
            for (int g = 0; g < 4; g++) {
                uint4 bw = s_dynW[((g * 64 + kt) << 5) + lane];
                mma_bf16(acc[g][0], AH, bw.x, bw.y);   // hi*hi
                mma_bf16(acc[g][1], AH, bw.z, bw.w);   // hi*lo
                mma_bf16(acc[g][1], AL, bw.x, bw.y);   // lo*hi
            }
        }
        #pragma unroll
        for (int g = 0; g < 4; g++) {
            zsm[ks][g][em][ec]         = acc[g][0][0] + acc[g][1][0];
            zsm[ks][g][em][ec + 1]     = acc[g][0][1] + acc[g][1][1];
            zsm[ks][g][em + 8][ec]     = acc[g][0][2] + acc[g][1][2];
            zsm[ks][g][em + 8][ec + 1] = acc[g][0][3] + acc[g][1][3];
        }
        __syncthreads();

        // ---- scalar: reduce k-slices, gates, c update, LN partial publish ----
        float zo = 0.f;
        if (tid < 256) {
            float zg[4];
            #pragma unroll
            for (int g = 0; g < 4; g++) {
                float s = zx_g[g];
                #pragma unroll
                for (int kss = 0; kss < 8; kss++) s += zsm[kss][g][tb][tn];
                zg[g] = s;
            }
            float ig = fast_exp(fminf(fmaxf(zg[0], -6.f), 3.f));
            float fg = fast_exp(fminf(fmaxf(zg[1], -6.f), 3.f));
            float cd = fast_tanh(zg[2]);
            zo = zg[3];
            c_reg = fg * c_reg + ig * cd;

            float s = c_reg, q = c_reg * c_reg;
            #pragma unroll
            for (int o = 1; o < 8; o <<= 1) {
                s += __shfl_xor_sync(0xffffffffu, s, o);
                q += __shfl_xor_sync(0xffffffffu, q, o);
            }
            if (tn == 0) *(float2*)&g_part[tb][bid][0] = make_float2(s, q);
        }

        grid_bar(ncalls);   // partials visible

        // ---- LN stats fully in registers + h ----
        if (tid < 256) {
            float ss = 0.f, qq = 0.f;
            #pragma unroll
            for (int i = 0; i < 16; i++) {
                float2 p = __ldcg((const float2*)&g_part[tb][tn + 8 * i][0]);
                ss += p.x; qq += p.y;
            }
            #pragma unroll
            for (int o = 1; o < 8; o <<= 1) {
                ss += __shfl_xor_sync(0xffffffffu, ss, o);
                qq += __shfl_xor_sync(0xffffffffu, qq, o);
            }
            float mu = ss * (1.f / HID);
            float rstd = rsqrtf(qq * (1.f / HID) - mu * mu + EPSV);
            float ln = (c_reg - mu) * rstd * gam + bet;
            float sg = fast_sigmoid(zo);
            float h = sg * fast_tanh(ln);
            __nv_bfloat16 hh, hl; split_f32(h, hh, hl);
            g_hf[funit + fj] = hh;
            g_hf[funit + 8 + fj] = hl;
            if (layer == 0) {
                size_t ri = ((size_t)t * BATCH + tb) * HID + hidx;
                g_hs_hi[ri] = hh; g_hs_lo[ri] = hl;
            }
            if (out && t == TSTEPS - 1) out[tb * HID + hidx] = h;
        }

        grid_bar(ncalls);   // h visible before next step's mma
    }
}

// ---------------------------------------------------------------------------
// Launch: 6 nodes
// ---------------------------------------------------------------------------
extern "C" void kernel_launch(void* const* d_in, const int* in_sizes, int n_in,
                              void* d_out, int out_size) {
    const float* series = (const float*)d_in[0];
    const float* W0 = (const float*)d_in[1];
    const float* b0 = (const float*)d_in[2];
    const float* g0 = (const float*)d_in[3];
    const float* be0 = (const float*)d_in[4];
    const float* W1 = (const float*)d_in[5];
    const float* b1 = (const float*)d_in[6];
    const float* g1 = (const float*)d_in[7];
    const float* be1 = (const float*)d_in[8];
    float* out = (float*)d_out;

    cudaFuncSetAttribute(k_recur, cudaFuncAttributeMaxDynamicSharedMemorySize, 131072);

    int nfrag = ((DIN / 16) + 3 * (HID / 16)) * NTILES * 32;
    k_split_all<<<(nfrag + 255) / 256, 256>>>(W0, W1);            // 1
    k_split_series<<<(MROWS * DIN + 255) / 256, 256>>>(series);   // 2
    k_pregemm<<<dim3(NOUT / 128, MROWS / 128), 512>>>(0, b0);     // 3 (+ init)
    k_recur<<<NB, 512, 131072>>>(0, g0, be0, nullptr);            // 4
    k_pregemm<<<dim3(NOUT / 128, MROWS / 128), 512>>>(1, b1);     // 5 (+ init)
    k_recur<<<NB, 512, 131072>>>(1, g1, be1, out);                // 6
}

// round 16
// speedup vs baseline: 1.0248x; 1.0248x over previous
#include <cuda_runtime.h>
#include <cuda_bf16.h>
#include <math.h>
#include <stdint.h>

#define BATCH 32
#define TSTEPS 256
#define DIN 256
#define HID 1024
#define NOUT 4096
#define MROWS (BATCH*TSTEPS)   // 8192
#define NTILES (NOUT/8)        // 512
#define NB 128                 // persistent grid size
#define EPSV 1e-5f

typedef unsigned int u32;

// ---------------------------------------------------------------------------
// Static device scratch (no allocations anywhere)
// ---------------------------------------------------------------------------
__device__ float           g_Z[(size_t)MROWS * NOUT];
__device__ __nv_bfloat16   g_Shi[(size_t)MROWS * DIN];
__device__ __nv_bfloat16   g_Slo[(size_t)MROWS * DIN];
__device__ __nv_bfloat16   g_hs_hi[(size_t)MROWS * HID];
__device__ __nv_bfloat16   g_hs_lo[(size_t)MROWS * HID];

// Fragment-swizzled weights: flat = ((kt*NTILES + nt)*32 + lane)*4 + j
__device__ __nv_bfloat16   g_W0x_hi[(size_t)DIN*NOUT], g_W0x_lo[(size_t)DIN*NOUT];
__device__ __nv_bfloat16   g_W0h_hi[(size_t)HID*NOUT], g_W0h_lo[(size_t)HID*NOUT];
__device__ __nv_bfloat16   g_W1x_hi[(size_t)HID*NOUT], g_W1x_lo[(size_t)HID*NOUT];
__device__ __nv_bfloat16   g_W1h_hi[(size_t)HID*NOUT], g_W1h_lo[(size_t)HID*NOUT];

// h in A-fragment layout: flat = ((mt*64 + kt)*32 + lane)*8 + j
__device__ __nv_bfloat16   g_hfh[BATCH*HID];
__device__ __nv_bfloat16   g_hfl[BATCH*HID];

// Spread barrier: 8 counters, 256 B apart (stride 64 u32). Block bid -> bid&7.
__device__ unsigned        g_cnt[8 * 64];
__device__ float           g_part[BATCH][NB][2];

// ---------------------------------------------------------------------------
// Primitives
// ---------------------------------------------------------------------------
__device__ __forceinline__ void mma_bf16(float acc[4], const u32 a[4], u32 b0, u32 b1) {
    asm volatile(
        "mma.sync.aligned.m16n8k16.row.col.f32.bf16.bf16.f32 "
        "{%0,%1,%2,%3},{%4,%5,%6,%7},{%8,%9},{%0,%1,%2,%3};\n"
        : "+f"(acc[0]), "+f"(acc[1]), "+f"(acc[2]), "+f"(acc[3])
        : "r"(a[0]), "r"(a[1]), "r"(a[2]), "r"(a[3]), "r"(b0), "r"(b1));
}

__device__ __forceinline__ void split_f32(float v, __nv_bfloat16& hi, __nv_bfloat16& lo) {
    hi = __float2bfloat16(v);
    lo = __float2bfloat16(v - __bfloat162float(hi));
}

__device__ __forceinline__ unsigned ld_acq(const unsigned* p) {
    unsigned v;
    asm volatile("ld.acquire.gpu.global.u32 %0, [%1];" : "=r"(v) : "l"(p) : "memory");
    return v;
}
__device__ __forceinline__ void red_rel_add1(unsigned* p) {
    asm volatile("red.release.gpu.global.add.u32 [%0], 1;" :: "l"(p) : "memory");
}

// Fast transcendentals (MUFU-based).
__device__ __forceinline__ float fast_exp(float x) { return __expf(x); }
__device__ __forceinline__ float fast_tanh(float x) {
    float e = __expf(2.f * x);
    return 1.f - __fdividef(2.f, e + 1.f);
}
__device__ __forceinline__ float fast_sigmoid(float x) {
    return __fdividef(1.f, 1.f + __expf(-x));
}

// ---------------------------------------------------------------------------
// Weight split, fragment-vectorized: one thread per (matrix, kt, nt, lane).
// ---------------------------------------------------------------------------
__global__ void k_split_all(const float* __restrict__ W0, const float* __restrict__ W1) {
    int tid = blockIdx.x * blockDim.x + threadIdx.x;
    const int f0 = (DIN / 16) * NTILES * 32;   // 262144
    const int f1 = (HID / 16) * NTILES * 32;   // 1048576
    if (tid >= f0 + 3 * f1) return;
    const float* W; int row0, fi;
    __nv_bfloat16 *dh, *dl;
    if (tid < f0)            { W = W0; row0 = 0;   dh = g_W0x_hi; dl = g_W0x_lo; fi = tid; }
    else if (tid < f0 + f1)  { W = W0; row0 = DIN; dh = g_W0h_hi; dl = g_W0h_lo; fi = tid - f0; }
    else if (tid < f0 + 2*f1){ W = W1; row0 = 0;   dh = g_W1x_hi; dl = g_W1x_lo; fi = tid - f0 - f1; }
    else                     { W = W1; row0 = HID; dh = g_W1h_hi; dl = g_W1h_lo; fi = tid - f0 - 2*f1; }
    int lane = fi & 31;
    int nt = (fi >> 5) & (NTILES - 1);
    int kt = fi >> 14;
    int n = nt * 8 + (lane >> 2);
    int l = lane & 3;
    ushort hb[4], lb[4];
    #pragma unroll
    for (int j = 0; j < 4; j++) {
        int kr = 2 * l + (j & 1) + ((j >> 1) << 3);
        float wv = W[(size_t)(row0 + kt * 16 + kr) * NOUT + n];
        __nv_bfloat16 hi, lo; split_f32(wv, hi, lo);
        hb[j] = __bfloat16_as_ushort(hi);
        lb[j] = __bfloat16_as_ushort(lo);
    }
    size_t base = (((size_t)kt * NTILES + nt) * 32 + lane) * 4;
    uint2 hv = make_uint2((u32)hb[0] | ((u32)hb[1] << 16), (u32)hb[2] | ((u32)hb[3] << 16));
    uint2 lv = make_uint2((u32)lb[0] | ((u32)lb[1] << 16), (u32)lb[2] | ((u32)lb[3] << 16));
    *(uint2*)(dh + base) = hv;
    *(uint2*)(dl + base) = lv;
}

// series [B,T,D] -> row-major [t*32+b, d] hi/lo
__global__ void k_split_series(const float* __restrict__ S) {
    int idx = blockIdx.x * blockDim.x + threadIdx.x;
    if (idx >= MROWS * DIN) return;
    int row = idx / DIN, d = idx - row * DIN;
    int t = row >> 5, b = row & 31;
    float v = S[((size_t)b * TSTEPS + t) * DIN + d];
    __nv_bfloat16 hi, lo; split_f32(v, hi, lo);
    g_Shi[idx] = hi; g_Slo[idx] = lo;
}

// ---------------------------------------------------------------------------
// Pregemm: M128 x N128 tiles, 512 thr (+ recurrent-state init in tail blocks)
// ---------------------------------------------------------------------------
__global__ __launch_bounds__(512) void k_pregemm(int which, const float* __restrict__ bias) {
    if (blockIdx.y == gridDim.y - 1 && blockIdx.x < 32) {
        int i = (blockIdx.x * 512 + threadIdx.x) * 2;
        __nv_bfloat16 z = __float2bfloat16(0.f);
        g_hfh[i] = z; g_hfh[i + 1] = z;
        g_hfl[i] = z; g_hfl[i + 1] = z;
        if (blockIdx.x == 0 && threadIdx.x < 8) g_cnt[threadIdx.x * 64] = 0;
    }

    const __nv_bfloat16 *Ah, *Al, *Wh, *Wl;
    int K;
    if (which == 0) { Ah = g_Shi; Al = g_Slo; Wh = g_W0x_hi; Wl = g_W0x_lo; K = DIN; }
    else            { Ah = g_hs_hi; Al = g_hs_lo; Wh = g_W1x_hi; Wl = g_W1x_lo; K = HID; }
    const int KT = K >> 4;

    int w = threadIdx.x >> 5, lane = threadIdx.x & 31;
    int ng = w & 1, mt = w >> 1;
    int m0 = blockIdx.y * 128, n0 = blockIdx.x * 128;
    int nt_base = (n0 >> 3) + ng * 8;

    float acc[8][4] = {};
    int rbase = m0 + mt * 16 + (lane >> 2);
    int cb = (lane & 3) << 1;

    #pragma unroll 2
    for (int kt = 0; kt < KT; kt++) {
        int c0 = kt * 16 + cb;
        const __nv_bfloat16* pa0 = Ah + (size_t)rbase * K + c0;
        const __nv_bfloat16* pa1 = Ah + (size_t)(rbase + 8) * K + c0;
        const __nv_bfloat16* pl0 = Al + (size_t)rbase * K + c0;
        const __nv_bfloat16* pl1 = Al + (size_t)(rbase + 8) * K + c0;
        u32 ah[4], al[4];
        ah[0] = *(const u32*)(pa0);     ah[1] = *(const u32*)(pa1);
        ah[2] = *(const u32*)(pa0 + 8); ah[3] = *(const u32*)(pa1 + 8);
        al[0] = *(const u32*)(pl0);     al[1] = *(const u32*)(pl1);
        al[2] = *(const u32*)(pl0 + 8); al[3] = *(const u32*)(pl1 + 8);
        #pragma unroll
        for (int q = 0; q < 8; q++) {
            size_t fb = (((size_t)kt * NTILES + (nt_base + q)) * 32 + lane) * 4;
            uint2 bh = *(const uint2*)(Wh + fb);
            uint2 bl = *(const uint2*)(Wl + fb);
            mma_bf16(acc[q], ah, bh.x, bh.y);
            mma_bf16(acc[q], ah, bl.x, bl.y);
            mma_bf16(acc[q], al, bh.x, bh.y);
        }
    }
    int r = rbase;
    #pragma unroll
    for (int q = 0; q < 8; q++) {
        int ncol = (nt_base + q) * 8 + cb;
        float b0v = bias[ncol], b1v = bias[ncol + 1];
        float* p0 = g_Z + (size_t)r * NOUT + ncol;
        float* p1 = g_Z + (size_t)(r + 8) * NOUT + ncol;
        p0[0] = acc[q][0] + b0v;  p0[1] = acc[q][1] + b1v;
        p1[0] = acc[q][2] + b0v;  p1[1] = acc[q][3] + b1v;
    }
}

// ---------------------------------------------------------------------------
// Grid barrier: 8 spread counters (best measured)
// ---------------------------------------------------------------------------
__device__ __forceinline__ void grid_bar(unsigned& ncalls) {
    ncalls += 1;
    __syncthreads();
    if (threadIdx.x < 32) {
        if (threadIdx.x == 0) red_rel_add1(&g_cnt[(blockIdx.x & 7) * 64]);
        unsigned tgt = ncalls * 16;
        const unsigned* p = &g_cnt[(threadIdx.x & 7) * 64];
        for (;;) {
            unsigned v = ld_acq(p);
            if (__all_sync(0xffffffffu, v >= tgt)) break;
        }
    }
    __syncthreads();
}

// ---------------------------------------------------------------------------
// Persistent recurrence: 128 blocks x 512 thr (16 warps). R12 optimum.
// ---------------------------------------------------------------------------
extern __shared__ uint4 s_dynW[];   // [4 gates][64 kt][32 lanes] uint4 = 128 KB

__global__ __launch_bounds__(512, 1) void k_recur(int layer,
                                                  const float* __restrict__ gamma,
                                                  const float* __restrict__ beta,
                                                  float* __restrict__ out) {
    const __nv_bfloat16* Wh = layer ? g_W1h_hi : g_W0h_hi;
    const __nv_bfloat16* Wl = layer ? g_W1h_lo : g_W0h_lo;
    const int bid = blockIdx.x;
    const int tid = threadIdx.x;

    for (int i = tid; i < 4 * 64 * 32; i += 512) {
        int lane = i & 31, kt = (i >> 5) & 63, g = i >> 11;
        size_t fb = (((size_t)kt * NTILES + (g * 128 + bid)) * 32 + lane);
        uint2 h2 = ((const uint2*)Wh)[fb];
        uint2 l2 = ((const uint2*)Wl)[fb];
        s_dynW[i] = make_uint4(h2.x, h2.y, l2.x, l2.y);
    }

    __shared__ float zsm[8][4][32][8];        // [ks][gate][row][col] partials

    const int w = tid >> 5, lane = tid & 31;
    const int mt = w & 1, ks = w >> 1;

    const int er = lane >> 2, ec = (lane & 3) << 1;
    const int em = mt * 16 + er;

    const int tb = (tid & 255) >> 3, tn = tid & 7;
    const int hidx = bid * 8 + tn;
    const float gam = gamma[hidx], bet = beta[hidx];
    float c_reg = 0.f;
    const int fmt = tb >> 4, fr = tb & 15, fkt = hidx >> 4, fc = hidx & 15;
    const int flane = (fr & 7) * 4 + ((fc & 7) >> 1);
    const int freg = ((fr >> 3) & 1) + ((fc >> 3) << 1);
    const size_t fout = (((size_t)fmt * 64 + fkt) * 32 + flane) * 8 + freg * 2 + (fc & 1);

    unsigned ncalls = 0;
    __syncthreads();

    for (int t = 0; t < TSTEPS; t++) {
        // prefetch zx for scalar phase (independent of h; g_Z never stale)
        float zx_g[4];
        if (tid < 256) {
            const float* zrow = g_Z + ((size_t)t * BATCH + tb) * NOUT + hidx;
            #pragma unroll
            for (int g = 0; g < 4; g++) zx_g[g] = zrow[g * 1024];
        }

        // ---- partial z = h @ Wh for k-slice ks, all 4 gates ----
        float acc[4][2][4] = {};
        #pragma unroll 2
        for (int kq = 0; kq < 8; kq++) {
            int kt = ks * 8 + kq;
            size_t fa = (((size_t)mt * 64 + kt) * 32 + lane) * 8;
            uint4 vh = __ldcg((const uint4*)(g_hfh + fa));
            uint4 vl = __ldcg((const uint4*)(g_hfl + fa));
            u32 AH[4] = {vh.x, vh.y, vh.z, vh.w};
            u32 AL[4] = {vl.x, vl.y, vl.z, vl.w};
            #pragma unroll
            for (int g = 0; g < 4; g++) {
                uint4 bw = s_dynW[((g * 64 + kt) << 5) + lane];
                mma_bf16(acc[g][0], AH, bw.x, bw.y);   // hi*hi
                mma_bf16(acc[g][1], AH, bw.z, bw.w);   // hi*lo
                mma_bf16(acc[g][1], AL, bw.x, bw.y);   // lo*hi
            }
        }
        #pragma unroll
        for (int g = 0; g < 4; g++) {
            zsm[ks][g][em][ec]         = acc[g][0][0] + acc[g][1][0];
            zsm[ks][g][em][ec + 1]     = acc[g][0][1] + acc[g][1][1];
            zsm[ks][g][em + 8][ec]     = acc[g][0][2] + acc[g][1][2];
            zsm[ks][g][em + 8][ec + 1] = acc[g][0][3] + acc[g][1][3];
        }
        __syncthreads();

        // ---- scalar: reduce k-slices, gates, c update, LN partial publish ----
        float zo = 0.f;
        if (tid < 256) {
            float zg[4];
            #pragma unroll
            for (int g = 0; g < 4; g++) {
                float s = zx_g[g];
                #pragma unroll
                for (int kss = 0; kss < 8; kss++) s += zsm[kss][g][tb][tn];
                zg[g] = s;
            }
            float ig = fast_exp(fminf(fmaxf(zg[0], -6.f), 3.f));
            float fg = fast_exp(fminf(fmaxf(zg[1], -6.f), 3.f));
            float cd = fast_tanh(zg[2]);
            zo = zg[3];
            c_reg = fg * c_reg + ig * cd;

            float s = c_reg, q = c_reg * c_reg;
            #pragma unroll
            for (int o = 1; o < 8; o <<= 1) {
                s += __shfl_xor_sync(0xffffffffu, s, o);
                q += __shfl_xor_sync(0xffffffffu, q, o);
            }
            if (tn == 0) *(float2*)&g_part[tb][bid][0] = make_float2(s, q);
        }

        grid_bar(ncalls);   // partials visible

        // ---- LN stats fully in registers + h ----
        if (tid < 256) {
            float ss = 0.f, qq = 0.f;
            #pragma unroll
            for (int i = 0; i < 16; i++) {
                float2 p = __ldcg((const float2*)&g_part[tb][tn + 8 * i][0]);
                ss += p.x; qq += p.y;
            }
            #pragma unroll
            for (int o = 1; o < 8; o <<= 1) {
                ss += __shfl_xor_sync(0xffffffffu, ss, o);
                qq += __shfl_xor_sync(0xffffffffu, qq, o);
            }
            float mu = ss * (1.f / HID);
            float rstd = rsqrtf(qq * (1.f / HID) - mu * mu + EPSV);
            float ln = (c_reg - mu) * rstd * gam + bet;
            float sg = fast_sigmoid(zo);
            float h = sg * fast_tanh(ln);
            __nv_bfloat16 hh, hl; split_f32(h, hh, hl);
            g_hfh[fout] = hh; g_hfl[fout] = hl;
            if (layer == 0) {
                size_t ri = ((size_t)t * BATCH + tb) * HID + hidx;
                g_hs_hi[ri] = hh; g_hs_lo[ri] = hl;
            }
            if (out && t == TSTEPS - 1) out[tb * HID + hidx] = h;
        }

        grid_bar(ncalls);   // h visible before next step's mma
    }
}

// ---------------------------------------------------------------------------
// Launch: 6 nodes
// ---------------------------------------------------------------------------
extern "C" void kernel_launch(void* const* d_in, const int* in_sizes, int n_in,
                              void* d_out, int out_size) {
    const float* series = (const float*)d_in[0];
    const float* W0 = (const float*)d_in[1];
    const float* b0 = (const float*)d_in[2];
    const float* g0 = (const float*)d_in[3];
    const float* be0 = (const float*)d_in[4];
    const float* W1 = (const float*)d_in[5];
    const float* b1 = (const float*)d_in[6];
    const float* g1 = (const float*)d_in[7];
    const float* be1 = (const float*)d_in[8];
    float* out = (float*)d_out;

    cudaFuncSetAttribute(k_recur, cudaFuncAttributeMaxDynamicSharedMemorySize, 131072);

    int nfrag = ((DIN / 16) + 3 * (HID / 16)) * NTILES * 32;
    k_split_all<<<(nfrag + 255) / 256, 256>>>(W0, W1);            // 1
    k_split_series<<<(MROWS * DIN + 255) / 256, 256>>>(series);   // 2
    k_pregemm<<<dim3(NOUT / 128, MROWS / 128), 512>>>(0, b0);     // 3 (+ init)
    k_recur<<<NB, 512, 131072>>>(0, g0, be0, nullptr);            // 4
    k_pregemm<<<dim3(NOUT / 128, MROWS / 128), 512>>>(1, b1);     // 5 (+ init)
    k_recur<<<NB, 512, 131072>>>(1, g1, be1, out);                // 6
}